// round 3
// baseline (speedup 1.0000x reference)
#include <cuda_runtime.h>
#include <cuda_bf16.h>
#include <cstdint>

// Problem constants
#define TT 4096      // B*S tokens
#define HH 1024      // hidden
#define II 2048      // intermediate
#define EE 8         // experts

#define BKP 20       // A smem row stride (16 + 4 pad) -> conflict-free frag LDS
#define BNP 136      // B smem row stride (128 + 8 pad) -> conflict-free frag LDS

// ---------------- scratch (device globals: no allocation allowed) ----------
__device__ float g_F[(size_t)2 * TT * II];      // 8192 x 2048 fused activations (64 MB)
__device__ float g_slot[(size_t)2 * TT * HH];   // 8192 x 1024 per-(token,k) outputs (32 MB)
__device__ int   g_cnt[EE];
__device__ int   g_rows[EE * TT];               // stores r = t*2 + k
__device__ float g_wts[EE * TT];

// ---------------- helpers ----------------
__device__ __forceinline__ unsigned f2tf(float f) {
    unsigned u;
    asm("cvt.rna.tf32.f32 %0, %1;" : "=r"(u) : "f"(f));
    return u;
}

__device__ __forceinline__ uint4 f2tf4(float4 v) {
    return make_uint4(f2tf(v.x), f2tf(v.y), f2tf(v.z), f2tf(v.w));
}

__device__ __forceinline__ void mma_tf32(float c[4], const unsigned a[4], const unsigned b[2]) {
    asm volatile(
        "mma.sync.aligned.m16n8k8.row.col.f32.tf32.tf32.f32 "
        "{%0,%1,%2,%3}, {%4,%5,%6,%7}, {%8,%9}, {%0,%1,%2,%3};\n"
        : "+f"(c[0]), "+f"(c[1]), "+f"(c[2]), "+f"(c[3])
        : "r"(a[0]), "r"(a[1]), "r"(a[2]), "r"(a[3]), "r"(b[0]), "r"(b[1]));
}

// ---------------- 0: zero expert counters ----------------
__global__ void zero_cnt_kernel() {
    if (threadIdx.x < EE) g_cnt[threadIdx.x] = 0;
}

// ---------------- 1: router (1 warp per token) ----------------
__global__ void router_kernel(const float* __restrict__ x, const float* __restrict__ Wg) {
    int t = (blockIdx.x * blockDim.x + threadIdx.x) >> 5;
    int lane = threadIdx.x & 31;
    if (t >= TT) return;
    const float* xr = x + (size_t)t * HH;
    float acc[EE];
#pragma unroll
    for (int e = 0; e < EE; e++) acc[e] = 0.f;
    for (int h = lane; h < HH; h += 32) {
        float xv = xr[h];
        const float4* wg = reinterpret_cast<const float4*>(Wg + h * EE);
        float4 w0 = wg[0], w1 = wg[1];
        acc[0] += xv * w0.x; acc[1] += xv * w0.y; acc[2] += xv * w0.z; acc[3] += xv * w0.w;
        acc[4] += xv * w1.x; acc[5] += xv * w1.y; acc[6] += xv * w1.z; acc[7] += xv * w1.w;
    }
#pragma unroll
    for (int off = 16; off > 0; off >>= 1) {
#pragma unroll
        for (int e = 0; e < EE; e++)
            acc[e] += __shfl_xor_sync(0xffffffffu, acc[e], off);
    }
    if (lane == 0) {
        float m = acc[0];
#pragma unroll
        for (int e = 1; e < EE; e++) m = fmaxf(m, acc[e]);
        float p[EE];
        float s = 0.f;
#pragma unroll
        for (int e = 0; e < EE; e++) { p[e] = __expf(acc[e] - m); s += p[e]; }
        float inv = 1.f / s;
        int i0 = 0;
#pragma unroll
        for (int e = 1; e < EE; e++) if (p[e] > p[i0]) i0 = e;
        int i1 = -1;
#pragma unroll
        for (int e = 0; e < EE; e++) {
            if (e == i0) continue;
            if (i1 < 0 || p[e] > p[i1]) i1 = e;
        }
        float s0 = p[i0] * inv, s1 = p[i1] * inv;
        float denom = s0 + s1 + 1e-8f;
        float w0 = s0 / denom, w1 = s1 / denom;
        int pos0 = atomicAdd(&g_cnt[i0], 1);
        g_rows[i0 * TT + pos0] = t * 2 + 0;
        g_wts[i0 * TT + pos0] = w0;
        int pos1 = atomicAdd(&g_cnt[i1], 1);
        g_rows[i1 * TT + pos1] = t * 2 + 1;
        g_wts[i1 * TT + pos1] = w1;
    }
}

// ---------------- 2: grouped GEMM1: F = SiLU(X@W11) * (X@W12) ----------------
// 128 threads, BM=64, BN=128, BK=16. Warps 2x2; warp tile 32x64, dual accum.
// grid: (II/128, 64, EE)
__global__ __launch_bounds__(128) void gemm1_kernel(
    const float* __restrict__ x,
    const float* __restrict__ W11,
    const float* __restrict__ W12)
{
    int e = blockIdx.z;
    int cnt = g_cnt[e];
    int m0 = blockIdx.y * 64;
    if (m0 >= cnt) return;
    int n0 = blockIdx.x * 128;

    __shared__ unsigned As[64][BKP];
    __shared__ unsigned B1s[16][BNP];
    __shared__ unsigned B2s[16][BNP];
    __shared__ int rloc[64];

    int tid = threadIdx.x;
    int lane = tid & 31;
    int warp = tid >> 5;
    int wm = (warp >> 1) * 32;     // 0 or 32
    int wn = (warp & 1) * 64;      // 0 or 64

    if (tid < 64) {
        int mi = m0 + tid;
        if (mi >= cnt) mi = cnt - 1;
        rloc[tid] = g_rows[e * TT + mi];
    }
    __syncthreads();

    float cG[2][8][4], cV[2][8][4];
#pragma unroll
    for (int a = 0; a < 2; a++)
#pragma unroll
        for (int b = 0; b < 8; b++)
#pragma unroll
            for (int c = 0; c < 4; c++) { cG[a][b][c] = 0.f; cV[a][b][c] = 0.f; }

    const float* W11base = W11 + (size_t)e * HH * II + n0;
    const float* W12base = W12 + (size_t)e * HH * II + n0;

    for (int kk = 0; kk < HH; kk += 16) {
        // A tile: 64x16 = 1024 words, 2 float4 per thread
#pragma unroll
        for (int p = 0; p < 2; p++) {
            int f = tid + p * 128;
            int row = f >> 2, cg = f & 3;
            int tok = rloc[row] >> 1;
            float4 v = *reinterpret_cast<const float4*>(x + (size_t)tok * HH + kk + cg * 4);
            *reinterpret_cast<uint4*>(&As[row][cg * 4]) = f2tf4(v);
        }
        // B tiles: 16x128 each, 4 float4 per thread per matrix
#pragma unroll
        for (int p = 0; p < 4; p++) {
            int f = tid + p * 128;
            int kr = f >> 5, cg = f & 31;
            size_t off = (size_t)(kk + kr) * II + cg * 4;
            float4 v1 = *reinterpret_cast<const float4*>(W11base + off);
            *reinterpret_cast<uint4*>(&B1s[kr][cg * 4]) = f2tf4(v1);
            float4 v2 = *reinterpret_cast<const float4*>(W12base + off);
            *reinterpret_cast<uint4*>(&B2s[kr][cg * 4]) = f2tf4(v2);
        }
        __syncthreads();

#pragma unroll
        for (int ks = 0; ks < 16; ks += 8) {
            unsigned a[2][4];
#pragma unroll
            for (int mt = 0; mt < 2; mt++) {
                int r = wm + mt * 16 + (lane >> 2);
                int cc = ks + (lane & 3);
                a[mt][0] = As[r][cc];
                a[mt][1] = As[r + 8][cc];
                a[mt][2] = As[r][cc + 4];
                a[mt][3] = As[r + 8][cc + 4];
            }
#pragma unroll
            for (int nt = 0; nt < 8; nt++) {
                int nc = wn + nt * 8 + (lane >> 2);
                int kr = ks + (lane & 3);
                unsigned b1[2] = { B1s[kr][nc], B1s[kr + 4][nc] };
                unsigned b2[2] = { B2s[kr][nc], B2s[kr + 4][nc] };
#pragma unroll
                for (int mt = 0; mt < 2; mt++) {
                    mma_tf32(cG[mt][nt], a[mt], b1);
                    mma_tf32(cV[mt][nt], a[mt], b2);
                }
            }
        }
        __syncthreads();
    }

    // epilogue: f = g * sigmoid(g) * v -> g_F[r]
#pragma unroll
    for (int mt = 0; mt < 2; mt++) {
#pragma unroll
        for (int half = 0; half < 2; half++) {
            int r = wm + mt * 16 + (lane >> 2) + half * 8;
            if (m0 + r < cnt) {
                int rg = rloc[r];
                float* dst = g_F + (size_t)rg * II + n0 + wn;
#pragma unroll
                for (int nt = 0; nt < 8; nt++) {
                    float g0 = cG[mt][nt][half * 2 + 0], g1 = cG[mt][nt][half * 2 + 1];
                    float v0 = cV[mt][nt][half * 2 + 0], v1 = cV[mt][nt][half * 2 + 1];
                    float f0 = g0 * v0 / (1.f + __expf(-g0));
                    float f1 = g1 * v1 / (1.f + __expf(-g1));
                    *reinterpret_cast<float2*>(dst + nt * 8 + (lane & 3) * 2) = make_float2(f0, f1);
                }
            }
        }
    }
}

// ---------------- 3: grouped GEMM2: O[r] = w[r] * (F[r] @ W2[e]) ----------------
// 128 threads, BM=128, BN=128, BK=16. Warps 2x2; warp tile 64x64.
// grid: (HH/128, 32, EE)
__global__ __launch_bounds__(128) void gemm2_kernel(const float* __restrict__ W2)
{
    int e = blockIdx.z;
    int cnt = g_cnt[e];
    int m0 = blockIdx.y * 128;
    if (m0 >= cnt) return;
    int n0 = blockIdx.x * 128;

    __shared__ unsigned As[128][BKP];
    __shared__ unsigned Bs[16][BNP];
    __shared__ int rloc[128];
    __shared__ float wloc[128];

    int tid = threadIdx.x;
    int lane = tid & 31;
    int warp = tid >> 5;
    int wm = (warp >> 1) * 64;     // 0 or 64
    int wn = (warp & 1) * 64;      // 0 or 64

    {
        int mi = m0 + tid;
        if (mi >= cnt) mi = cnt - 1;
        rloc[tid] = g_rows[e * TT + mi];
        wloc[tid] = g_wts[e * TT + mi];
    }
    __syncthreads();

    float c[4][8][4];
#pragma unroll
    for (int a = 0; a < 4; a++)
#pragma unroll
        for (int b = 0; b < 8; b++)
#pragma unroll
            for (int cc = 0; cc < 4; cc++) c[a][b][cc] = 0.f;

    const float* Bbase = W2 + (size_t)e * II * HH + n0;

    for (int kk = 0; kk < II; kk += 16) {
        // A tile: 128x16 = 2048 words, 4 float4 per thread (gathered g_F rows)
#pragma unroll
        for (int p = 0; p < 4; p++) {
            int f = tid + p * 128;
            int row = f >> 2, cg = f & 3;
            float4 v = *reinterpret_cast<const float4*>(g_F + (size_t)rloc[row] * II + kk + cg * 4);
            *reinterpret_cast<uint4*>(&As[row][cg * 4]) = f2tf4(v);
        }
        // B tile: 16x128, 4 float4 per thread
#pragma unroll
        for (int p = 0; p < 4; p++) {
            int f = tid + p * 128;
            int kr = f >> 5, cg = f & 31;
            float4 v = *reinterpret_cast<const float4*>(Bbase + (size_t)(kk + kr) * HH + cg * 4);
            *reinterpret_cast<uint4*>(&Bs[kr][cg * 4]) = f2tf4(v);
        }
        __syncthreads();

#pragma unroll
        for (int ks = 0; ks < 16; ks += 8) {
            unsigned a[4][4];
#pragma unroll
            for (int mt = 0; mt < 4; mt++) {
                int r = wm + mt * 16 + (lane >> 2);
                int cc = ks + (lane & 3);
                a[mt][0] = As[r][cc];
                a[mt][1] = As[r + 8][cc];
                a[mt][2] = As[r][cc + 4];
                a[mt][3] = As[r + 8][cc + 4];
            }
#pragma unroll
            for (int nt = 0; nt < 8; nt++) {
                int nc = wn + nt * 8 + (lane >> 2);
                int kr = ks + (lane & 3);
                unsigned b[2] = { Bs[kr][nc], Bs[kr + 4][nc] };
#pragma unroll
                for (int mt = 0; mt < 4; mt++)
                    mma_tf32(c[mt][nt], a[mt], b);
            }
        }
        __syncthreads();
    }

    // epilogue: scale by routing weight, scatter to slot buffer
#pragma unroll
    for (int mt = 0; mt < 4; mt++) {
#pragma unroll
        for (int half = 0; half < 2; half++) {
            int r = wm + mt * 16 + (lane >> 2) + half * 8;
            if (m0 + r < cnt) {
                int rg = rloc[r];
                float wr = wloc[r];
                float* dst = g_slot + (size_t)rg * HH + n0 + wn;
#pragma unroll
                for (int nt = 0; nt < 8; nt++) {
                    float o0 = wr * c[mt][nt][half * 2 + 0];
                    float o1 = wr * c[mt][nt][half * 2 + 1];
                    *reinterpret_cast<float2*>(dst + nt * 8 + (lane & 3) * 2) = make_float2(o0, o1);
                }
            }
        }
    }
}

// ---------------- 4: combine the two expert slots per token ----------------
__global__ void combine_kernel(float* __restrict__ out) {
    int i = blockIdx.x * blockDim.x + threadIdx.x;   // float4 index
    const int n4 = TT * HH / 4;
    if (i >= n4) return;
    int t = i / (HH / 4);
    int h4 = i % (HH / 4);
    float4 a = reinterpret_cast<const float4*>(g_slot + (size_t)(2 * t) * HH)[h4];
    float4 b = reinterpret_cast<const float4*>(g_slot + (size_t)(2 * t + 1) * HH)[h4];
    float4 r = make_float4(a.x + b.x, a.y + b.y, a.z + b.z, a.w + b.w);
    reinterpret_cast<float4*>(out)[i] = r;
}

// ---------------- launch ----------------
extern "C" void kernel_launch(void* const* d_in, const int* in_sizes, int n_in,
                              void* d_out, int out_size) {
    (void)in_sizes; (void)n_in; (void)out_size;
    const float* x   = (const float*)d_in[0];
    const float* Wg  = (const float*)d_in[1];
    const float* W11 = (const float*)d_in[2];
    const float* W12 = (const float*)d_in[3];
    const float* W2  = (const float*)d_in[4];
    float* out = (float*)d_out;

    zero_cnt_kernel<<<1, 32>>>();
    router_kernel<<<TT / 4, 128>>>(x, Wg);                 // 4 warps/block

    dim3 g1(II / 128, TT / 64, EE);                        // (16, 64, 8)
    gemm1_kernel<<<g1, 128>>>(x, W11, W12);

    dim3 g2(HH / 128, TT / 128, EE);                       // (8, 32, 8)
    gemm2_kernel<<<g2, 128>>>(W2);

    combine_kernel<<<(TT * HH / 4 + 255) / 256, 256>>>(out);
}

// round 8
// speedup vs baseline: 1.8415x; 1.8415x over previous
#include <cuda_runtime.h>
#include <cstdint>

// Problem constants
#define TT 4096      // B*S tokens
#define HH 1024      // hidden
#define II 2048      // intermediate
#define EE 8         // experts

#define AKP 20       // A smem row stride (16 + 4 pad) words; 80B = 5*16 -> cp.async 16B aligned
#define BNP 136      // B smem row stride (128 + 8 pad) words; 544B = 34*16

// ---------------- scratch (device globals: no allocation allowed) ----------
__device__ float g_F[(size_t)2 * TT * II];      // 8192 x 2048 fused activations (64 MB)
__device__ float g_slot[(size_t)2 * TT * HH];   // 8192 x 1024 per-(token,k) outputs (32 MB)
__device__ int   g_cnt[EE];
__device__ int   g_rows[EE * TT];               // stores r = t*2 + k
__device__ float g_wts[EE * TT];

// ---------------- helpers ----------------
__device__ __forceinline__ unsigned f2tf(float f) {
    unsigned u;
    asm("cvt.rna.tf32.f32 %0, %1;" : "=r"(u) : "f"(f));
    return u;
}

__device__ __forceinline__ void cp16(float* smem_dst, const float* gmem_src) {
    unsigned s = (unsigned)__cvta_generic_to_shared(smem_dst);
    asm volatile("cp.async.cg.shared.global [%0], [%1], 16;\n" :: "r"(s), "l"(gmem_src));
}
#define CP_COMMIT() asm volatile("cp.async.commit_group;\n" ::: "memory")
#define CP_WAIT0()  asm volatile("cp.async.wait_group 0;\n" ::: "memory")
#define CP_WAIT1()  asm volatile("cp.async.wait_group 1;\n" ::: "memory")

__device__ __forceinline__ void mma_tf32(float c[4], const unsigned a[4], const unsigned b[2]) {
    asm volatile(
        "mma.sync.aligned.m16n8k8.row.col.f32.tf32.tf32.f32 "
        "{%0,%1,%2,%3}, {%4,%5,%6,%7}, {%8,%9}, {%0,%1,%2,%3};\n"
        : "+f"(c[0]), "+f"(c[1]), "+f"(c[2]), "+f"(c[3])
        : "r"(a[0]), "r"(a[1]), "r"(a[2]), "r"(a[3]), "r"(b[0]), "r"(b[1]));
}

// ---------------- 0: zero expert counters ----------------
__global__ void zero_cnt_kernel() {
    if (threadIdx.x < EE) g_cnt[threadIdx.x] = 0;
}

// ---------------- 1: router (1 warp per token) ----------------
__global__ void router_kernel(const float* __restrict__ x, const float* __restrict__ Wg) {
    int t = (blockIdx.x * blockDim.x + threadIdx.x) >> 5;
    int lane = threadIdx.x & 31;
    if (t >= TT) return;
    const float* xr = x + (size_t)t * HH;
    float acc[EE];
#pragma unroll
    for (int e = 0; e < EE; e++) acc[e] = 0.f;
    for (int h = lane; h < HH; h += 32) {
        float xv = xr[h];
        const float4* wg = reinterpret_cast<const float4*>(Wg + h * EE);
        float4 w0 = wg[0], w1 = wg[1];
        acc[0] += xv * w0.x; acc[1] += xv * w0.y; acc[2] += xv * w0.z; acc[3] += xv * w0.w;
        acc[4] += xv * w1.x; acc[5] += xv * w1.y; acc[6] += xv * w1.z; acc[7] += xv * w1.w;
    }
#pragma unroll
    for (int off = 16; off > 0; off >>= 1) {
#pragma unroll
        for (int e = 0; e < EE; e++)
            acc[e] += __shfl_xor_sync(0xffffffffu, acc[e], off);
    }
    if (lane == 0) {
        float m = acc[0];
#pragma unroll
        for (int e = 1; e < EE; e++) m = fmaxf(m, acc[e]);
        float p[EE];
        float s = 0.f;
#pragma unroll
        for (int e = 0; e < EE; e++) { p[e] = __expf(acc[e] - m); s += p[e]; }
        float inv = 1.f / s;
        int i0 = 0;
#pragma unroll
        for (int e = 1; e < EE; e++) if (p[e] > p[i0]) i0 = e;
        int i1 = -1;
#pragma unroll
        for (int e = 0; e < EE; e++) {
            if (e == i0) continue;
            if (i1 < 0 || p[e] > p[i1]) i1 = e;
        }
        float s0 = p[i0] * inv, s1 = p[i1] * inv;
        float denom = s0 + s1 + 1e-8f;
        float w0 = s0 / denom, w1 = s1 / denom;
        int pos0 = atomicAdd(&g_cnt[i0], 1);
        g_rows[i0 * TT + pos0] = t * 2 + 0;
        g_wts[i0 * TT + pos0] = w0;
        int pos1 = atomicAdd(&g_cnt[i1], 1);
        g_rows[i1 * TT + pos1] = t * 2 + 1;
        g_wts[i1 * TT + pos1] = w1;
    }
}

// ---------------- 2: grouped GEMM1: F = SiLU(X@W11) * (X@W12) ----------------
// 256 threads. BM=64, BN=128, BK=16, double-buffered cp.async.
// Warps 2(m) x 4(n); warp tile 32x32, dual accumulators (G and V).
// grid: (II/128, TT/64, EE)
__global__ __launch_bounds__(256, 2) void gemm1_kernel(
    const float* __restrict__ x,
    const float* __restrict__ W11,
    const float* __restrict__ W12)
{
    int e = blockIdx.z;
    int cnt = g_cnt[e];
    int m0 = blockIdx.y * 64;
    if (m0 >= cnt) return;
    int n0 = blockIdx.x * 128;

    __shared__ float As[2][64][AKP];
    __shared__ float B1s[2][16][BNP];
    __shared__ float B2s[2][16][BNP];
    __shared__ int rloc[64];

    int tid = threadIdx.x;
    int lane = tid & 31;
    int warp = tid >> 5;
    int wm = (warp >> 2) * 32;     // 0 or 32
    int wn = (warp & 3) * 32;      // 0,32,64,96

    if (tid < 64) {
        int mi = m0 + tid;
        if (mi >= cnt) mi = cnt - 1;
        rloc[tid] = g_rows[e * TT + mi];
    }
    __syncthreads();

    const float* W11base = W11 + (size_t)e * HH * II + n0;
    const float* W12base = W12 + (size_t)e * HH * II + n0;

    // per-thread staging coordinates
    int a_row = tid >> 2, a_cg = (tid & 3) * 4;          // 256 threads cover 64x4 chunks
    int b_kr0 = tid >> 5, b_cg = (tid & 31) * 4;         // +8 rows for second pass
    int a_tok = rloc[a_row] >> 1;

    float cG[2][4][4], cV[2][4][4];
#pragma unroll
    for (int a = 0; a < 2; a++)
#pragma unroll
        for (int b = 0; b < 4; b++)
#pragma unroll
            for (int c = 0; c < 4; c++) { cG[a][b][c] = 0.f; cV[a][b][c] = 0.f; }

    const int NIT = HH / 16;

    // prologue: prefetch k-tile 0 into buffer 0
    cp16(&As[0][a_row][a_cg], x + (size_t)a_tok * HH + a_cg);
#pragma unroll
    for (int p = 0; p < 2; p++) {
        int kr = b_kr0 + p * 8;
        cp16(&B1s[0][kr][b_cg], W11base + (size_t)kr * II + b_cg);
        cp16(&B2s[0][kr][b_cg], W12base + (size_t)kr * II + b_cg);
    }
    CP_COMMIT();

    for (int it = 0; it < NIT; it++) {
        int buf = it & 1;
        if (it + 1 < NIT) {
            int kk = (it + 1) * 16;
            cp16(&As[buf ^ 1][a_row][a_cg], x + (size_t)a_tok * HH + kk + a_cg);
#pragma unroll
            for (int p = 0; p < 2; p++) {
                int kr = b_kr0 + p * 8;
                cp16(&B1s[buf ^ 1][kr][b_cg], W11base + (size_t)(kk + kr) * II + b_cg);
                cp16(&B2s[buf ^ 1][kr][b_cg], W12base + (size_t)(kk + kr) * II + b_cg);
            }
            CP_COMMIT();
            CP_WAIT1();   // current tile's group done; prefetch may remain in flight
        } else {
            CP_WAIT0();
        }
        __syncthreads();

#pragma unroll
        for (int ks = 0; ks < 16; ks += 8) {
            unsigned a[2][4];
#pragma unroll
            for (int mt = 0; mt < 2; mt++) {
                int r = wm + mt * 16 + (lane >> 2);
                int cc = ks + (lane & 3);
                a[mt][0] = f2tf(As[buf][r][cc]);
                a[mt][1] = f2tf(As[buf][r + 8][cc]);
                a[mt][2] = f2tf(As[buf][r][cc + 4]);
                a[mt][3] = f2tf(As[buf][r + 8][cc + 4]);
            }
#pragma unroll
            for (int nt = 0; nt < 4; nt++) {
                int nc = wn + nt * 8 + (lane >> 2);
                int kr = ks + (lane & 3);
                unsigned b1[2] = { f2tf(B1s[buf][kr][nc]), f2tf(B1s[buf][kr + 4][nc]) };
                unsigned b2[2] = { f2tf(B2s[buf][kr][nc]), f2tf(B2s[buf][kr + 4][nc]) };
#pragma unroll
                for (int mt = 0; mt < 2; mt++) {
                    mma_tf32(cG[mt][nt], a[mt], b1);
                    mma_tf32(cV[mt][nt], a[mt], b2);
                }
            }
        }
        __syncthreads();
    }

    // epilogue: f = g * sigmoid(g) * v -> g_F[r]
#pragma unroll
    for (int mt = 0; mt < 2; mt++) {
#pragma unroll
        for (int half = 0; half < 2; half++) {
            int r = wm + mt * 16 + (lane >> 2) + half * 8;
            if (m0 + r < cnt) {
                int rg = rloc[r];
                float* dst = g_F + (size_t)rg * II + n0 + wn;
#pragma unroll
                for (int nt = 0; nt < 4; nt++) {
                    float g0 = cG[mt][nt][half * 2 + 0], g1 = cG[mt][nt][half * 2 + 1];
                    float v0 = cV[mt][nt][half * 2 + 0], v1 = cV[mt][nt][half * 2 + 1];
                    float f0 = g0 * v0 / (1.f + __expf(-g0));
                    float f1 = g1 * v1 / (1.f + __expf(-g1));
                    *reinterpret_cast<float2*>(dst + nt * 8 + (lane & 3) * 2) = make_float2(f0, f1);
                }
            }
        }
    }
}

// ---------------- 3: grouped GEMM2: O[r] = w[r] * (F[r] @ W2[e]) ----------------
// 256 threads. BM=128, BN=128, BK=16, double-buffered cp.async.
// Warps 2(m) x 4(n); warp tile 64x32.
// grid: (HH/128, TT/128, EE)
__global__ __launch_bounds__(256, 2) void gemm2_kernel(const float* __restrict__ W2)
{
    int e = blockIdx.z;
    int cnt = g_cnt[e];
    int m0 = blockIdx.y * 128;
    if (m0 >= cnt) return;
    int n0 = blockIdx.x * 128;

    __shared__ float As[2][128][AKP];
    __shared__ float Bs[2][16][BNP];
    __shared__ int rloc[128];
    __shared__ float wloc[128];

    int tid = threadIdx.x;
    int lane = tid & 31;
    int warp = tid >> 5;
    int wm = (warp >> 2) * 64;     // 0 or 64
    int wn = (warp & 3) * 32;      // 0,32,64,96

    if (tid < 128) {
        int mi = m0 + tid;
        if (mi >= cnt) mi = cnt - 1;
        rloc[tid] = g_rows[e * TT + mi];
        wloc[tid] = g_wts[e * TT + mi];
    }
    __syncthreads();

    const float* Bbase = W2 + (size_t)e * II * HH + n0;

    // staging coords: A has 128x4 = 512 chunks -> 2/thread; B 16x32 = 512 -> 2/thread
    int a_row0 = tid >> 2, a_cg = (tid & 3) * 4;         // rows tid>>2 and +64
    int b_kr0 = tid >> 5, b_cg = (tid & 31) * 4;
    int a_r0 = rloc[a_row0];
    int a_r1 = rloc[a_row0 + 64];

    float c[4][4][4];
#pragma unroll
    for (int a = 0; a < 4; a++)
#pragma unroll
        for (int b = 0; b < 4; b++)
#pragma unroll
            for (int cc = 0; cc < 4; cc++) c[a][b][cc] = 0.f;

    const int NIT = II / 16;

    cp16(&As[0][a_row0][a_cg], g_F + (size_t)a_r0 * II + a_cg);
    cp16(&As[0][a_row0 + 64][a_cg], g_F + (size_t)a_r1 * II + a_cg);
#pragma unroll
    for (int p = 0; p < 2; p++) {
        int kr = b_kr0 + p * 8;
        cp16(&Bs[0][kr][b_cg], Bbase + (size_t)kr * HH + b_cg);
    }
    CP_COMMIT();

    for (int it = 0; it < NIT; it++) {
        int buf = it & 1;
        if (it + 1 < NIT) {
            int kk = (it + 1) * 16;
            cp16(&As[buf ^ 1][a_row0][a_cg], g_F + (size_t)a_r0 * II + kk + a_cg);
            cp16(&As[buf ^ 1][a_row0 + 64][a_cg], g_F + (size_t)a_r1 * II + kk + a_cg);
#pragma unroll
            for (int p = 0; p < 2; p++) {
                int kr = b_kr0 + p * 8;
                cp16(&Bs[buf ^ 1][kr][b_cg], Bbase + (size_t)(kk + kr) * HH + b_cg);
            }
            CP_COMMIT();
            CP_WAIT1();
        } else {
            CP_WAIT0();
        }
        __syncthreads();

#pragma unroll
        for (int ks = 0; ks < 16; ks += 8) {
            unsigned a[4][4];
#pragma unroll
            for (int mt = 0; mt < 4; mt++) {
                int r = wm + mt * 16 + (lane >> 2);
                int cc = ks + (lane & 3);
                a[mt][0] = f2tf(As[buf][r][cc]);
                a[mt][1] = f2tf(As[buf][r + 8][cc]);
                a[mt][2] = f2tf(As[buf][r][cc + 4]);
                a[mt][3] = f2tf(As[buf][r + 8][cc + 4]);
            }
#pragma unroll
            for (int nt = 0; nt < 4; nt++) {
                int nc = wn + nt * 8 + (lane >> 2);
                int kr = ks + (lane & 3);
                unsigned b[2] = { f2tf(Bs[buf][kr][nc]), f2tf(Bs[buf][kr + 4][nc]) };
#pragma unroll
                for (int mt = 0; mt < 4; mt++)
                    mma_tf32(c[mt][nt], a[mt], b);
            }
        }
        __syncthreads();
    }

    // epilogue: scale by routing weight, scatter to slot buffer
#pragma unroll
    for (int mt = 0; mt < 4; mt++) {
#pragma unroll
        for (int half = 0; half < 2; half++) {
            int r = wm + mt * 16 + (lane >> 2) + half * 8;
            if (m0 + r < cnt) {
                int rg = rloc[r];
                float wr = wloc[r];
                float* dst = g_slot + (size_t)rg * HH + n0 + wn;
#pragma unroll
                for (int nt = 0; nt < 4; nt++) {
                    float o0 = wr * c[mt][nt][half * 2 + 0];
                    float o1 = wr * c[mt][nt][half * 2 + 1];
                    *reinterpret_cast<float2*>(dst + nt * 8 + (lane & 3) * 2) = make_float2(o0, o1);
                }
            }
        }
    }
}

// ---------------- 4: combine the two expert slots per token ----------------
__global__ void combine_kernel(float* __restrict__ out) {
    int i = blockIdx.x * blockDim.x + threadIdx.x;   // float4 index
    const int n4 = TT * HH / 4;
    if (i >= n4) return;
    int t = i / (HH / 4);
    int h4 = i % (HH / 4);
    float4 a = reinterpret_cast<const float4*>(g_slot + (size_t)(2 * t) * HH)[h4];
    float4 b = reinterpret_cast<const float4*>(g_slot + (size_t)(2 * t + 1) * HH)[h4];
    float4 r = make_float4(a.x + b.x, a.y + b.y, a.z + b.z, a.w + b.w);
    reinterpret_cast<float4*>(out)[i] = r;
}

// ---------------- launch ----------------
extern "C" void kernel_launch(void* const* d_in, const int* in_sizes, int n_in,
                              void* d_out, int out_size) {
    (void)in_sizes; (void)n_in; (void)out_size;
    const float* x   = (const float*)d_in[0];
    const float* Wg  = (const float*)d_in[1];
    const float* W11 = (const float*)d_in[2];
    const float* W12 = (const float*)d_in[3];
    const float* W2  = (const float*)d_in[4];
    float* out = (float*)d_out;

    zero_cnt_kernel<<<1, 32>>>();
    router_kernel<<<TT / 4, 128>>>(x, Wg);                 // 4 warps/block

    dim3 g1(II / 128, TT / 64, EE);                        // (16, 64, 8)
    gemm1_kernel<<<g1, 256>>>(x, W11, W12);

    dim3 g2(HH / 128, TT / 128, EE);                       // (8, 32, 8)
    gemm2_kernel<<<g2, 256>>>(W2);

    combine_kernel<<<(TT * HH / 4 + 255) / 256, 256>>>(out);
}